// round 15
// baseline (speedup 1.0000x reference)
#include <cuda_runtime.h>
#include <cuda_fp16.h>
#include <cstdint>

#define BB   8
#define DD   128
#define KK   7
#define QQ   256
#define G0V  511
#define KP   512
#define G1V  512
#define F1V  512
#define F2V  1024
#define OUTC 16

// ---------------- scratch (static device arrays, no alloc APIs) -------------
__device__ __half g_u_h[BB * DD * KP];   // c-part (incl g0_b), col 511 = 0
__device__ __half g_v_h[BB * DD * KP];   // a-part, col 511 = 0
__device__ __half g_wt[G1V * KP];        // W^T fp16 [n][k], k>=511 = 0
__device__ float g_qc[BB * G1V];         // qst @ g1_w[511:767] + g1_b
__device__ float g_part[BB * DD * G1V];  // per (b,a) col sums
__device__ float g_h1[BB * F1V];
__device__ float g_h2[BB * F2V];

// ---------------- helpers ----------------------------------------------------
__device__ __forceinline__ uint32_t smem_u32(const void* p) {
    uint32_t a;
    asm("{ .reg .u64 t; cvta.to.shared.u64 t, %1; cvt.u32.u64 %0, t; }" : "=r"(a) : "l"(p));
    return a;
}
__device__ __forceinline__ uint32_t relu_add2h(uint32_t ua, uint32_t va) {
    __half2 x = __hadd2(*reinterpret_cast<__half2*>(&ua),
                        *reinterpret_cast<__half2*>(&va));
    x = __hmax2(x, __float2half2_rn(0.f));
    return *reinterpret_cast<uint32_t*>(&x);
}

#define LDMX4(r0, r1, r2, r3, addr) \
    asm volatile("ldmatrix.sync.aligned.m8n8.x4.shared.b16 {%0,%1,%2,%3}, [%4];" \
        : "=r"(r0), "=r"(r1), "=r"(r2), "=r"(r3) : "r"(addr))

#define MMA_F16(c, A, b0, b1) \
    asm volatile("mma.sync.aligned.m16n8k16.row.col.f32.f16.f16.f32 " \
        "{%0,%1,%2,%3},{%4,%5,%6,%7},{%8,%9},{%0,%1,%2,%3};" \
        : "+f"((c)[0]), "+f"((c)[1]), "+f"((c)[2]), "+f"((c)[3]) \
        : "r"((A)[0]), "r"((A)[1]), "r"((A)[2]), "r"((A)[3]), "r"(b0), "r"(b1))

#define CP_ASYNC16(dst, src) \
    asm volatile("cp.async.cg.shared.global [%0], [%1], 16;" :: "r"(dst), "l"(src) : "memory")
#define CP_COMMIT() asm volatile("cp.async.commit_group;" ::: "memory")
#define CP_WAIT1()  asm volatile("cp.async.wait_group 1;" ::: "memory")

// ---------------- merged prep kernel ----------------------------------------
// grid = 1024 (uv) + 8 (qc) + 64 (W-transpose tiles), 512 threads.
__global__ void prep_all_kernel(const float* __restrict__ x,
                                const float* __restrict__ g0w,
                                const float* __restrict__ g0b,
                                const float* __restrict__ g1w,
                                const float* __restrict__ qst,
                                const float* __restrict__ g1b) {
    const int bid = blockIdx.x;
    const int t = threadIdx.x;
    __shared__ float xs[KK];
    __shared__ float qs[QQ];
    __shared__ __half tile[64 * 72];

    if (bid < BB * DD) {
        // ---- u / v
        if (t < KK) xs[t] = x[bid * KK + t];
        __syncthreads();
        float u = 0.f, v = 0.f;
        if (t < G0V) {
            u = g0b[t];
#pragma unroll
            for (int k = 0; k < KK; ++k) {
                u += xs[k] * g0w[k * G0V + t];
                v += xs[k] * g0w[(k + KK) * G0V + t];
            }
        }
        g_u_h[bid * KP + t] = __float2half(u);
        g_v_h[bid * KP + t] = __float2half(v);
    } else if (bid < BB * DD + BB) {
        // ---- qc
        const int b = bid - BB * DD;
        if (t < QQ) qs[t] = qst[b * QQ + t];
        __syncthreads();
        float s = g1b[t];
#pragma unroll 4
        for (int q = 0; q < QQ; ++q)
            s += qs[q] * g1w[(G0V + q) * G1V + t];
        g_qc[b * G1V + t] = s;
    } else {
        // ---- W transpose: 64x64 tile, coalesced read + coalesced write
        const int wb = bid - (BB * DD + BB);        // 0..63
        const int kt = (wb >> 3) * 64, nt = (wb & 7) * 64;
        const int w = t >> 5, lane = t & 31;        // 16 warps
#pragma unroll
        for (int i = 0; i < 4; ++i) {
            const int r = w * 4 + i;
            const int k = kt + r;
            float2 v = make_float2(0.f, 0.f);
            if (k < G0V) v = *(const float2*)(g1w + (size_t)k * G1V + nt + lane * 2);
            tile[r * 72 + lane * 2]     = __float2half(v.x);
            tile[r * 72 + lane * 2 + 1] = __float2half(v.y);
        }
        __syncthreads();
#pragma unroll
        for (int i = 0; i < 4; ++i) {
            const int nl = w * 4 + i;
            __half2 h = __halves2half2(tile[(lane * 2) * 72 + nl],
                                       tile[(lane * 2 + 1) * 72 + nl]);
            *(__half2*)(g_wt + (size_t)(nt + nl) * KP + kt + lane * 2) = h;
        }
    }
}

// ---------------- dominant kernel: 3-stage pipelined HMMA GEMM (fp16) -------
// (round-7 best configuration, unchanged)
#define OFF_V      0
#define OFF_QC     2048
#define OFF_RED    2560
#define OFF_STAGE  6784
#define T_PITCH    80
#define TILE_SZ    (128 * T_PITCH)      // 10240
#define STAGE_SZ   (3 * TILE_SZ)        // A0 A1 W = 30720
#define NSTAGE     3
#define SMEM_MMA_TOTAL (OFF_STAGE + NSTAGE * STAGE_SZ)   // 98944

__global__ __launch_bounds__(512, 1) void rn_mma_kernel() {
    extern __shared__ char smem[];
    const uint32_t sbase = smem_u32(smem);
    const int t = threadIdx.x;
    const int lane = t & 31, warp = t >> 5;
    const int wc = warp >> 2, wn = warp & 3;
    const int nq = blockIdx.x, ap = blockIdx.y, b = blockIdx.z;

    if (t < 128) {
        ((uint4*)smem)[t] =
            ((const uint4*)(g_v_h + (size_t)(b * DD + ap * 2) * KP))[t];
    } else if (t < 256) {
        ((float*)(smem + OFF_QC))[t - 128] = g_qc[b * G1V + nq * 128 + (t - 128)];
    }

    const int row = t >> 2, seg = t & 3;
    const __half* uptr = g_u_h + (size_t)(b * DD + row) * KP + seg * 8;
    const __half* wptr = g_wt  + (size_t)(nq * 128 + row) * KP + seg * 8;
    const uint32_t arow = (uint32_t)row * T_PITCH + seg * 16;

    auto stAddr = [&](int s) { return sbase + OFF_STAGE + s * STAGE_SZ; };

    auto buildA = [&](int kb, int s, const uint4& uu) {
        char* sb = smem + OFF_STAGE + s * STAGE_SZ;
        uint4 v0 = *(const uint4*)(smem + kb * 64 + seg * 16);
        uint4 v1 = *(const uint4*)(smem + 1024 + kb * 64 + seg * 16);
        uint4 a0, a1;
        a0.x = relu_add2h(uu.x, v0.x); a0.y = relu_add2h(uu.y, v0.y);
        a0.z = relu_add2h(uu.z, v0.z); a0.w = relu_add2h(uu.w, v0.w);
        a1.x = relu_add2h(uu.x, v1.x); a1.y = relu_add2h(uu.y, v1.y);
        a1.z = relu_add2h(uu.z, v1.z); a1.w = relu_add2h(uu.w, v1.w);
        *(uint4*)(sb + arow)           = a0;
        *(uint4*)(sb + TILE_SZ + arow) = a1;
    };

    const int grp = lane >> 3, rin = lane & 7;
    const uint32_t aOff = (uint32_t)(wc * 32 + rin + (grp & 1) * 8) * T_PITCH + (grp >> 1) * 16;
    const uint32_t bOff = (uint32_t)(wn * 32 + rin + (grp >> 1) * 8) * T_PITCH + (grp & 1) * 16;

    float acc[2][2][4][4];
#pragma unroll
    for (int a = 0; a < 2; ++a)
#pragma unroll
        for (int mi = 0; mi < 2; ++mi)
#pragma unroll
            for (int ni = 0; ni < 4; ++ni)
#pragma unroll
                for (int j = 0; j < 4; ++j) acc[a][mi][ni][j] = 0.f;

    CP_ASYNC16(stAddr(0) + 2 * TILE_SZ + arow, wptr);
    CP_COMMIT();
    CP_ASYNC16(stAddr(1) + 2 * TILE_SZ + arow, wptr + 32);
    CP_COMMIT();
    __syncthreads();
    {
        uint4 uu = *(const uint4*)(uptr);
        buildA(0, 0, uu);
    }
    CP_WAIT1();
    __syncthreads();

    uint4 pu;
    for (int it = 0; it < 16; ++it) {
        const uint32_t sb = stAddr(it % NSTAGE);
        if (it + 2 < 16) {
            const uint32_t nst = stAddr((it + 2) % NSTAGE);
            CP_ASYNC16(nst + 2 * TILE_SZ + arow, wptr + (it + 2) * 32);
        }
        CP_COMMIT();
        if (it + 1 < 16) pu = *(const uint4*)(uptr + (it + 1) * 32);

#pragma unroll
        for (int kk = 0; kk < 2; ++kk) {
            uint32_t BW[4][2];
            const uint32_t bwA = sb + 2 * TILE_SZ + bOff + kk * 32;
            LDMX4(BW[0][0], BW[0][1], BW[1][0], BW[1][1], bwA);
            LDMX4(BW[2][0], BW[2][1], BW[3][0], BW[3][1], bwA + 16 * T_PITCH);
#pragma unroll
            for (int a = 0; a < 2; ++a) {
                uint32_t AF[2][4];
                const uint32_t aa = sb + a * TILE_SZ + aOff + kk * 32;
                LDMX4(AF[0][0], AF[0][1], AF[0][2], AF[0][3], aa);
                LDMX4(AF[1][0], AF[1][1], AF[1][2], AF[1][3], aa + 16 * T_PITCH);
#pragma unroll
                for (int mi = 0; mi < 2; ++mi)
#pragma unroll
                    for (int ni = 0; ni < 4; ++ni)
                        MMA_F16(acc[a][mi][ni], AF[mi], BW[ni][0], BW[ni][1]);
            }
        }
        if (it + 1 < 16) buildA(it + 1, (it + 1) % NSTAGE, pu);
        CP_WAIT1();
        __syncthreads();
    }

    // ---- epilogue: relu(D + qc), sum over c (deterministic) ----
    const float* qcs = (const float*)(smem + OFF_QC);
    float* red = (float*)(smem + OFF_RED);
    float qn0[4], qn1[4];
    const int nc0 = wn * 32 + (lane & 3) * 2;
#pragma unroll
    for (int ni = 0; ni < 4; ++ni) {
        qn0[ni] = qcs[nc0 + ni * 8];
        qn1[ni] = qcs[nc0 + ni * 8 + 1];
    }
#pragma unroll
    for (int a = 0; a < 2; ++a) {
        float s0[4], s1[4];
#pragma unroll
        for (int ni = 0; ni < 4; ++ni) {
            s0[ni] = 0.f; s1[ni] = 0.f;
#pragma unroll
            for (int mi = 0; mi < 2; ++mi) {
                s0[ni] += fmaxf(acc[a][mi][ni][0] + qn0[ni], 0.f)
                        + fmaxf(acc[a][mi][ni][2] + qn0[ni], 0.f);
                s1[ni] += fmaxf(acc[a][mi][ni][1] + qn1[ni], 0.f)
                        + fmaxf(acc[a][mi][ni][3] + qn1[ni], 0.f);
            }
        }
#pragma unroll
        for (int off = 4; off < 32; off <<= 1)
#pragma unroll
            for (int ni = 0; ni < 4; ++ni) {
                s0[ni] += __shfl_xor_sync(0xffffffffu, s0[ni], off);
                s1[ni] += __shfl_xor_sync(0xffffffffu, s1[ni], off);
            }
        if (lane < 4) {
#pragma unroll
            for (int ni = 0; ni < 4; ++ni) {
                red[(wc * 2 + a) * 128 + wn * 32 + ni * 8 + lane * 2]     = s0[ni];
                red[(wc * 2 + a) * 128 + wn * 32 + ni * 8 + lane * 2 + 1] = s1[ni];
            }
        }
    }
    __syncthreads();
    if (t < 256) {
        const int a = t >> 7, n = t & 127;
        float s = 0.f;
#pragma unroll
        for (int w = 0; w < 4; ++w) s += red[(w * 2 + a) * 128 + n];
        g_part[((size_t)(b * DD) + ap * 2 + a) * G1V + nq * 128 + n] = s;
    }
}

// ---------------- tail kernels -----------------------------------------------
// k_f1 (fused xg): grid (4 nq, 8 b), 1024 thr.
// Phase 1: xg[i] = sum_a part[b,a,i] (2 thr/entry, 64 a each, fixed order).
// Phase 2: f1 outputs nq*128..+127 with 8-way split-K over smem xg.
__global__ __launch_bounds__(1024) void k_f1(const float* __restrict__ f1w,
                                             const float* __restrict__ f1b) {
    const int nq = blockIdx.x, b = blockIdx.y;
    const int t = threadIdx.x;   // 1024
    __shared__ float xs[G1V];
    __shared__ float red[1024];

    // ---- phase 1: xg
    {
        const int i = t & 511, half = t >> 9;     // 2 threads per entry
        const float* p = g_part + ((size_t)(b * DD) + half * 64) * G1V + i;
        float s = 0.f;
#pragma unroll 16
        for (int a = 0; a < 64; ++a) s += p[(size_t)a * G1V];
        red[t] = s;
    }
    __syncthreads();
    if (t < G1V) xs[t] = red[t] + red[t + 512];
    __syncthreads();

    // ---- phase 2: f1, 8 threads/output, K split 8x64
    const int j = nq * 128 + (t & 127);
    const int q = t >> 7, base = q * 64;   // q 0..7
    float s = 0.f;
#pragma unroll 16
    for (int i = 0; i < 64; ++i)
        s += xs[base + i] * f1w[(size_t)(base + i) * F1V + j];
    red[t] = s;
    __syncthreads();
    if (t < 128) {
        float r = f1b[nq * 128 + t];
#pragma unroll
        for (int q2 = 0; q2 < 8; ++q2) r += red[q2 * 128 + t];
        g_h1[b * F1V + nq * 128 + t] = fmaxf(r, 0.f);
    }
}

// k_f2: grid (8 jb, 8 b), 1024 thr; 8 threads/output, K split 8x64.
__global__ __launch_bounds__(1024) void k_f2(const float* __restrict__ f2w,
                                             const float* __restrict__ f2b) {
    const int jb = blockIdx.x, b = blockIdx.y;
    const int t = threadIdx.x;   // 1024
    __shared__ float hs[F1V];
    __shared__ float red[1024];
    if (t < F1V) hs[t] = g_h1[b * F1V + t];
    __syncthreads();
    const int j = jb * 128 + (t & 127);
    const int q = t >> 7, base = q * 64;
    float s = 0.f;
#pragma unroll 16
    for (int i = 0; i < 64; ++i)
        s += hs[base + i] * f2w[(size_t)(base + i) * F2V + j];
    red[t] = s;
    __syncthreads();
    if (t < 128) {
        float r = f2b[jb * 128 + t];
#pragma unroll
        for (int q2 = 0; q2 < 8; ++q2) r += red[q2 * 128 + t];
        g_h2[b * F2V + jb * 128 + t] = fmaxf(r, 0.f);
    }
}

__global__ void k_f3(const float* __restrict__ f3w, const float* __restrict__ f3b,
                     float* __restrict__ out) {
    const int b = blockIdx.x;
    const int t = threadIdx.x;   // 256
    __shared__ float h2s[F2V];
    __shared__ float lp[16 * OUTC];
    __shared__ float lg[OUTC];
    for (int i = t; i < F2V; i += 256) h2s[i] = g_h2[b * F2V + i];
    __syncthreads();
    {
        const int o  = t & 15;
        const int ch = t >> 4;
        float acc = (ch == 0) ? f3b[o] : 0.f;
#pragma unroll 16
        for (int i = ch * 64; i < ch * 64 + 64; ++i)
            acc += h2s[i] * f3w[i * OUTC + o];
        lp[ch * OUTC + o] = acc;
    }
    __syncthreads();
    if (t < OUTC) {
        float s = 0.f;
#pragma unroll
        for (int ch = 0; ch < 16; ++ch) s += lp[ch * OUTC + t];
        lg[t] = s;
    }
    __syncthreads();
    if (t < OUTC) {
        float m = lg[0];
#pragma unroll
        for (int i = 1; i < OUTC; ++i) m = fmaxf(m, lg[i]);
        float se = 0.f;
#pragma unroll
        for (int i = 0; i < OUTC; ++i) se += expf(lg[i] - m);
        out[b * OUTC + t] = lg[t] - m - logf(se);
    }
}

// ---------------- launch -----------------------------------------------------
extern "C" void kernel_launch(void* const* d_in, const int* in_sizes, int n_in,
                              void* d_out, int out_size) {
    const float* x   = (const float*)d_in[0];
    const float* qst = (const float*)d_in[1];
    const float* g0w = (const float*)d_in[2];
    const float* g0b = (const float*)d_in[3];
    const float* g1w = (const float*)d_in[4];
    const float* g1b = (const float*)d_in[5];
    const float* f1w = (const float*)d_in[6];
    const float* f1b = (const float*)d_in[7];
    const float* f2w = (const float*)d_in[8];
    const float* f2b = (const float*)d_in[9];
    const float* f3w = (const float*)d_in[10];
    const float* f3b = (const float*)d_in[11];
    float* out = (float*)d_out;

    static bool attr_set = false;
    if (!attr_set) {
        cudaFuncSetAttribute(rn_mma_kernel,
                             cudaFuncAttributeMaxDynamicSharedMemorySize, SMEM_MMA_TOTAL);
        attr_set = true;
    }

    prep_all_kernel<<<BB * DD + BB + 64, 512>>>(x, g0w, g0b, g1w, qst, g1b);
    rn_mma_kernel<<<dim3(4, 64, BB), 512, SMEM_MMA_TOTAL>>>();
    k_f1<<<dim3(4, BB), 1024>>>(f1w, f1b);
    k_f2<<<dim3(8, BB), 1024>>>(f2w, f2b);
    k_f3<<<BB, 256>>>(f3w, f3b, out);
}

// round 16
// speedup vs baseline: 1.0165x; 1.0165x over previous
#include <cuda_runtime.h>
#include <cuda_fp16.h>
#include <cstdint>

#define BB   8
#define DD   128
#define KK   7
#define QQ   256
#define G0V  511
#define KP   512
#define G1V  512
#define F1V  512
#define F2V  1024
#define OUTC 16

// ---------------- scratch (static device arrays, no alloc APIs) -------------
__device__ __half g_u_h[BB * DD * KP];   // c-part (incl g0_b), col 511 = 0
__device__ __half g_v_h[BB * DD * KP];   // a-part, col 511 = 0
__device__ __half g_wt[G1V * KP];        // W^T fp16 [n][k], k>=511 = 0
__device__ float g_qc[BB * G1V];         // qst @ g1_w[511:767] + g1_b
__device__ float g_part[BB * 64 * G1V];  // per (b, a-pair) col sums
__device__ float g_xg[BB * G1V];
__device__ float g_h1[BB * F1V];
__device__ float g_h2[BB * F2V];

// ---------------- helpers ----------------------------------------------------
__device__ __forceinline__ uint32_t smem_u32(const void* p) {
    uint32_t a;
    asm("{ .reg .u64 t; cvta.to.shared.u64 t, %1; cvt.u32.u64 %0, t; }" : "=r"(a) : "l"(p));
    return a;
}
__device__ __forceinline__ uint32_t relu_add2h(uint32_t ua, uint32_t va) {
    __half2 x = __hadd2(*reinterpret_cast<__half2*>(&ua),
                        *reinterpret_cast<__half2*>(&va));
    x = __hmax2(x, __float2half2_rn(0.f));
    return *reinterpret_cast<uint32_t*>(&x);
}

#define LDMX4(r0, r1, r2, r3, addr) \
    asm volatile("ldmatrix.sync.aligned.m8n8.x4.shared.b16 {%0,%1,%2,%3}, [%4];" \
        : "=r"(r0), "=r"(r1), "=r"(r2), "=r"(r3) : "r"(addr))

#define MMA_F16(c, A, b0, b1) \
    asm volatile("mma.sync.aligned.m16n8k16.row.col.f32.f16.f16.f32 " \
        "{%0,%1,%2,%3},{%4,%5,%6,%7},{%8,%9},{%0,%1,%2,%3};" \
        : "+f"((c)[0]), "+f"((c)[1]), "+f"((c)[2]), "+f"((c)[3]) \
        : "r"((A)[0]), "r"((A)[1]), "r"((A)[2]), "r"((A)[3]), "r"(b0), "r"(b1))

#define CP_ASYNC16(dst, src) \
    asm volatile("cp.async.cg.shared.global [%0], [%1], 16;" :: "r"(dst), "l"(src) : "memory")
#define CP_COMMIT() asm volatile("cp.async.commit_group;" ::: "memory")
#define CP_WAIT1()  asm volatile("cp.async.wait_group 1;" ::: "memory")

// ---------------- merged prep kernel ----------------------------------------
// grid = 1024 (uv) + 8 (qc) + 64 (W-transpose tiles), 512 threads.
__global__ void prep_all_kernel(const float* __restrict__ x,
                                const float* __restrict__ g0w,
                                const float* __restrict__ g0b,
                                const float* __restrict__ g1w,
                                const float* __restrict__ qst,
                                const float* __restrict__ g1b) {
    const int bid = blockIdx.x;
    const int t = threadIdx.x;
    __shared__ float xs[KK];
    __shared__ float qs[QQ];
    __shared__ __half tile[64 * 72];

    if (bid < BB * DD) {
        // ---- u / v
        if (t < KK) xs[t] = x[bid * KK + t];
        __syncthreads();
        float u = 0.f, v = 0.f;
        if (t < G0V) {
            u = g0b[t];
#pragma unroll
            for (int k = 0; k < KK; ++k) {
                u += xs[k] * g0w[k * G0V + t];
                v += xs[k] * g0w[(k + KK) * G0V + t];
            }
        }
        g_u_h[bid * KP + t] = __float2half(u);
        g_v_h[bid * KP + t] = __float2half(v);
    } else if (bid < BB * DD + BB) {
        // ---- qc
        const int b = bid - BB * DD;
        if (t < QQ) qs[t] = qst[b * QQ + t];
        __syncthreads();
        float s = g1b[t];
#pragma unroll 4
        for (int q = 0; q < QQ; ++q)
            s += qs[q] * g1w[(G0V + q) * G1V + t];
        g_qc[b * G1V + t] = s;
    } else {
        // ---- W transpose: 64x64 tile, coalesced read + coalesced write
        const int wb = bid - (BB * DD + BB);        // 0..63
        const int kt = (wb >> 3) * 64, nt = (wb & 7) * 64;
        const int w = t >> 5, lane = t & 31;        // 16 warps
#pragma unroll
        for (int i = 0; i < 4; ++i) {
            const int r = w * 4 + i;
            const int k = kt + r;
            float2 v = make_float2(0.f, 0.f);
            if (k < G0V) v = *(const float2*)(g1w + (size_t)k * G1V + nt + lane * 2);
            tile[r * 72 + lane * 2]     = __float2half(v.x);
            tile[r * 72 + lane * 2 + 1] = __float2half(v.y);
        }
        __syncthreads();
#pragma unroll
        for (int i = 0; i < 4; ++i) {
            const int nl = w * 4 + i;
            __half2 h = __halves2half2(tile[(lane * 2) * 72 + nl],
                                       tile[(lane * 2 + 1) * 72 + nl]);
            *(__half2*)(g_wt + (size_t)(nt + nl) * KP + kt + lane * 2) = h;
        }
    }
}

// ---------------- dominant kernel: 3-stage pipelined HMMA GEMM (fp16) -------
// (round-7 best configuration; epilogue now pre-reduces the a-pair)
#define OFF_V      0
#define OFF_QC     2048
#define OFF_RED    2560
#define OFF_STAGE  6784
#define T_PITCH    80
#define TILE_SZ    (128 * T_PITCH)      // 10240
#define STAGE_SZ   (3 * TILE_SZ)        // A0 A1 W = 30720
#define NSTAGE     3
#define SMEM_MMA_TOTAL (OFF_STAGE + NSTAGE * STAGE_SZ)   // 98944

__global__ __launch_bounds__(512, 1) void rn_mma_kernel() {
    extern __shared__ char smem[];
    const uint32_t sbase = smem_u32(smem);
    const int t = threadIdx.x;
    const int lane = t & 31, warp = t >> 5;
    const int wc = warp >> 2, wn = warp & 3;
    const int nq = blockIdx.x, ap = blockIdx.y, b = blockIdx.z;

    if (t < 128) {
        ((uint4*)smem)[t] =
            ((const uint4*)(g_v_h + (size_t)(b * DD + ap * 2) * KP))[t];
    } else if (t < 256) {
        ((float*)(smem + OFF_QC))[t - 128] = g_qc[b * G1V + nq * 128 + (t - 128)];
    }

    const int row = t >> 2, seg = t & 3;
    const __half* uptr = g_u_h + (size_t)(b * DD + row) * KP + seg * 8;
    const __half* wptr = g_wt  + (size_t)(nq * 128 + row) * KP + seg * 8;
    const uint32_t arow = (uint32_t)row * T_PITCH + seg * 16;

    auto stAddr = [&](int s) { return sbase + OFF_STAGE + s * STAGE_SZ; };

    auto buildA = [&](int kb, int s, const uint4& uu) {
        char* sb = smem + OFF_STAGE + s * STAGE_SZ;
        uint4 v0 = *(const uint4*)(smem + kb * 64 + seg * 16);
        uint4 v1 = *(const uint4*)(smem + 1024 + kb * 64 + seg * 16);
        uint4 a0, a1;
        a0.x = relu_add2h(uu.x, v0.x); a0.y = relu_add2h(uu.y, v0.y);
        a0.z = relu_add2h(uu.z, v0.z); a0.w = relu_add2h(uu.w, v0.w);
        a1.x = relu_add2h(uu.x, v1.x); a1.y = relu_add2h(uu.y, v1.y);
        a1.z = relu_add2h(uu.z, v1.z); a1.w = relu_add2h(uu.w, v1.w);
        *(uint4*)(sb + arow)           = a0;
        *(uint4*)(sb + TILE_SZ + arow) = a1;
    };

    const int grp = lane >> 3, rin = lane & 7;
    const uint32_t aOff = (uint32_t)(wc * 32 + rin + (grp & 1) * 8) * T_PITCH + (grp >> 1) * 16;
    const uint32_t bOff = (uint32_t)(wn * 32 + rin + (grp >> 1) * 8) * T_PITCH + (grp & 1) * 16;

    float acc[2][2][4][4];
#pragma unroll
    for (int a = 0; a < 2; ++a)
#pragma unroll
        for (int mi = 0; mi < 2; ++mi)
#pragma unroll
            for (int ni = 0; ni < 4; ++ni)
#pragma unroll
                for (int j = 0; j < 4; ++j) acc[a][mi][ni][j] = 0.f;

    CP_ASYNC16(stAddr(0) + 2 * TILE_SZ + arow, wptr);
    CP_COMMIT();
    CP_ASYNC16(stAddr(1) + 2 * TILE_SZ + arow, wptr + 32);
    CP_COMMIT();
    __syncthreads();
    {
        uint4 uu = *(const uint4*)(uptr);
        buildA(0, 0, uu);
    }
    CP_WAIT1();
    __syncthreads();

    uint4 pu;
    for (int it = 0; it < 16; ++it) {
        const uint32_t sb = stAddr(it % NSTAGE);
        if (it + 2 < 16) {
            const uint32_t nst = stAddr((it + 2) % NSTAGE);
            CP_ASYNC16(nst + 2 * TILE_SZ + arow, wptr + (it + 2) * 32);
        }
        CP_COMMIT();
        if (it + 1 < 16) pu = *(const uint4*)(uptr + (it + 1) * 32);

#pragma unroll
        for (int kk = 0; kk < 2; ++kk) {
            uint32_t BW[4][2];
            const uint32_t bwA = sb + 2 * TILE_SZ + bOff + kk * 32;
            LDMX4(BW[0][0], BW[0][1], BW[1][0], BW[1][1], bwA);
            LDMX4(BW[2][0], BW[2][1], BW[3][0], BW[3][1], bwA + 16 * T_PITCH);
#pragma unroll
            for (int a = 0; a < 2; ++a) {
                uint32_t AF[2][4];
                const uint32_t aa = sb + a * TILE_SZ + aOff + kk * 32;
                LDMX4(AF[0][0], AF[0][1], AF[0][2], AF[0][3], aa);
                LDMX4(AF[1][0], AF[1][1], AF[1][2], AF[1][3], aa + 16 * T_PITCH);
#pragma unroll
                for (int mi = 0; mi < 2; ++mi)
#pragma unroll
                    for (int ni = 0; ni < 4; ++ni)
                        MMA_F16(acc[a][mi][ni], AF[mi], BW[ni][0], BW[ni][1]);
            }
        }
        if (it + 1 < 16) buildA(it + 1, (it + 1) % NSTAGE, pu);
        CP_WAIT1();
        __syncthreads();
    }

    // ---- epilogue: relu(D + qc), sum over c AND the a-pair (deterministic) --
    const float* qcs = (const float*)(smem + OFF_QC);
    float* red = (float*)(smem + OFF_RED);
    float qn0[4], qn1[4];
    const int nc0 = wn * 32 + (lane & 3) * 2;
#pragma unroll
    for (int ni = 0; ni < 4; ++ni) {
        qn0[ni] = qcs[nc0 + ni * 8];
        qn1[ni] = qcs[nc0 + ni * 8 + 1];
    }
#pragma unroll
    for (int a = 0; a < 2; ++a) {
        float s0[4], s1[4];
#pragma unroll
        for (int ni = 0; ni < 4; ++ni) {
            s0[ni] = 0.f; s1[ni] = 0.f;
#pragma unroll
            for (int mi = 0; mi < 2; ++mi) {
                s0[ni] += fmaxf(acc[a][mi][ni][0] + qn0[ni], 0.f)
                        + fmaxf(acc[a][mi][ni][2] + qn0[ni], 0.f);
                s1[ni] += fmaxf(acc[a][mi][ni][1] + qn1[ni], 0.f)
                        + fmaxf(acc[a][mi][ni][3] + qn1[ni], 0.f);
            }
        }
#pragma unroll
        for (int off = 4; off < 32; off <<= 1)
#pragma unroll
            for (int ni = 0; ni < 4; ++ni) {
                s0[ni] += __shfl_xor_sync(0xffffffffu, s0[ni], off);
                s1[ni] += __shfl_xor_sync(0xffffffffu, s1[ni], off);
            }
        if (lane < 4) {
#pragma unroll
            for (int ni = 0; ni < 4; ++ni) {
                red[(wc * 2 + a) * 128 + wn * 32 + ni * 8 + lane * 2]     = s0[ni];
                red[(wc * 2 + a) * 128 + wn * 32 + ni * 8 + lane * 2 + 1] = s1[ni];
            }
        }
    }
    __syncthreads();
    if (t < 128) {
        float s = 0.f;
#pragma unroll
        for (int r = 0; r < 8; ++r) s += red[r * 128 + t];
        g_part[((size_t)(b * 64) + ap) * G1V + nq * 128 + t] = s;
    }
}

// ---------------- tail kernels (R14 best shapes) -----------------------------
// k_xg: grid (4 nq, 8 b), 1024 thr; 8 threads/output over ap-chunks of 8.
__global__ __launch_bounds__(1024) void k_xg() {
    const int nq = blockIdx.x, b = blockIdx.y;
    const int t = threadIdx.x;   // 1024
    const int n = t & 127, aq = t >> 7;   // aq 0..7
    __shared__ float red[1024];
    const float* p = g_part + ((size_t)(b * 64) + aq * 8) * G1V + nq * 128 + n;
    float s = 0.f;
#pragma unroll
    for (int a = 0; a < 8; ++a) s += p[(size_t)a * G1V];
    red[aq * 128 + n] = s;
    __syncthreads();
    if (t < 128) {
        float r = 0.f;
#pragma unroll
        for (int q = 0; q < 8; ++q) r += red[q * 128 + t];
        g_xg[b * G1V + nq * 128 + t] = r;
    }
}

// k_f1: grid (4 nq, 8 b), 1024 thr; 8 threads/output, K split 8x64.
__global__ __launch_bounds__(1024) void k_f1(const float* __restrict__ f1w,
                                             const float* __restrict__ f1b) {
    const int nq = blockIdx.x, b = blockIdx.y;
    const int t = threadIdx.x;   // 1024
    __shared__ float xs[G1V];
    __shared__ float red[1024];
    if (t < G1V) xs[t] = g_xg[b * G1V + t];
    __syncthreads();
    const int j = nq * 128 + (t & 127);
    const int q = t >> 7, base = q * 64;   // q 0..7
    float s = 0.f;
#pragma unroll 16
    for (int i = 0; i < 64; ++i)
        s += xs[base + i] * f1w[(size_t)(base + i) * F1V + j];
    red[t] = s;
    __syncthreads();
    if (t < 128) {
        float r = f1b[nq * 128 + t];
#pragma unroll
        for (int q2 = 0; q2 < 8; ++q2) r += red[q2 * 128 + t];
        g_h1[b * F1V + nq * 128 + t] = fmaxf(r, 0.f);
    }
}

// k_f2: grid (8 jb, 8 b), 1024 thr; 8 threads/output, K split 8x64.
__global__ __launch_bounds__(1024) void k_f2(const float* __restrict__ f2w,
                                             const float* __restrict__ f2b) {
    const int jb = blockIdx.x, b = blockIdx.y;
    const int t = threadIdx.x;   // 1024
    __shared__ float hs[F1V];
    __shared__ float red[1024];
    if (t < F1V) hs[t] = g_h1[b * F1V + t];
    __syncthreads();
    const int j = jb * 128 + (t & 127);
    const int q = t >> 7, base = q * 64;
    float s = 0.f;
#pragma unroll 16
    for (int i = 0; i < 64; ++i)
        s += hs[base + i] * f2w[(size_t)(base + i) * F2V + j];
    red[t] = s;
    __syncthreads();
    if (t < 128) {
        float r = f2b[jb * 128 + t];
#pragma unroll
        for (int q2 = 0; q2 < 8; ++q2) r += red[q2 * 128 + t];
        g_h2[b * F2V + jb * 128 + t] = fmaxf(r, 0.f);
    }
}

__global__ void k_f3(const float* __restrict__ f3w, const float* __restrict__ f3b,
                     float* __restrict__ out) {
    const int b = blockIdx.x;
    const int t = threadIdx.x;   // 256
    __shared__ float h2s[F2V];
    __shared__ float lp[16 * OUTC];
    __shared__ float lg[OUTC];
    for (int i = t; i < F2V; i += 256) h2s[i] = g_h2[b * F2V + i];
    __syncthreads();
    {
        const int o  = t & 15;
        const int ch = t >> 4;
        float acc = (ch == 0) ? f3b[o] : 0.f;
#pragma unroll 16
        for (int i = ch * 64; i < ch * 64 + 64; ++i)
            acc += h2s[i] * f3w[i * OUTC + o];
        lp[ch * OUTC + o] = acc;
    }
    __syncthreads();
    if (t < OUTC) {
        float s = 0.f;
#pragma unroll
        for (int ch = 0; ch < 16; ++ch) s += lp[ch * OUTC + t];
        lg[t] = s;
    }
    __syncthreads();
    if (t < OUTC) {
        float m = lg[0];
#pragma unroll
        for (int i = 1; i < OUTC; ++i) m = fmaxf(m, lg[i]);
        float se = 0.f;
#pragma unroll
        for (int i = 0; i < OUTC; ++i) se += expf(lg[i] - m);
        out[b * OUTC + t] = lg[t] - m - logf(se);
    }
}

// ---------------- launch -----------------------------------------------------
extern "C" void kernel_launch(void* const* d_in, const int* in_sizes, int n_in,
                              void* d_out, int out_size) {
    const float* x   = (const float*)d_in[0];
    const float* qst = (const float*)d_in[1];
    const float* g0w = (const float*)d_in[2];
    const float* g0b = (const float*)d_in[3];
    const float* g1w = (const float*)d_in[4];
    const float* g1b = (const float*)d_in[5];
    const float* f1w = (const float*)d_in[6];
    const float* f1b = (const float*)d_in[7];
    const float* f2w = (const float*)d_in[8];
    const float* f2b = (const float*)d_in[9];
    const float* f3w = (const float*)d_in[10];
    const float* f3b = (const float*)d_in[11];
    float* out = (float*)d_out;

    static bool attr_set = false;
    if (!attr_set) {
        cudaFuncSetAttribute(rn_mma_kernel,
                             cudaFuncAttributeMaxDynamicSharedMemorySize, SMEM_MMA_TOTAL);
        attr_set = true;
    }

    prep_all_kernel<<<BB * DD + BB + 64, 512>>>(x, g0w, g0b, g1w, qst, g1b);
    rn_mma_kernel<<<dim3(4, 64, BB), 512, SMEM_MMA_TOTAL>>>();
    k_xg<<<dim3(4, BB), 1024>>>();
    k_f1<<<dim3(4, BB), 1024>>>(f1w, f1b);
    k_f2<<<dim3(8, BB), 1024>>>(f2w, f2b);
    k_f3<<<BB, 256>>>(f3w, f3b, out);
}

// round 17
// speedup vs baseline: 1.0174x; 1.0008x over previous
#include <cuda_runtime.h>
#include <cuda_fp16.h>
#include <cstdint>

#define BB   8
#define DD   128
#define KK   7
#define QQ   256
#define G0V  511
#define KP   512
#define G1V  512
#define F1V  512
#define F2V  1024
#define OUTC 16

// ---------------- scratch (static device arrays, no alloc APIs) -------------
__device__ __half g_u_h[BB * DD * KP];   // c-part (incl g0_b), col 511 = 0
__device__ __half g_v_h[BB * DD * KP];   // a-part, col 511 = 0
__device__ __half g_wt[G1V * KP];        // W^T fp16 [n][k], k>=511 = 0
__device__ float g_qc[BB * G1V];         // qst @ g1_w[511:767] + g1_b
__device__ float g_part[BB * 64 * G1V];  // per (b, a-pair) col sums
__device__ float g_h1[BB * F1V];
__device__ float g_h2[BB * F2V];

// ---------------- helpers ----------------------------------------------------
__device__ __forceinline__ uint32_t smem_u32(const void* p) {
    uint32_t a;
    asm("{ .reg .u64 t; cvta.to.shared.u64 t, %1; cvt.u32.u64 %0, t; }" : "=r"(a) : "l"(p));
    return a;
}
__device__ __forceinline__ uint32_t relu_add2h(uint32_t ua, uint32_t va) {
    __half2 x = __hadd2(*reinterpret_cast<__half2*>(&ua),
                        *reinterpret_cast<__half2*>(&va));
    x = __hmax2(x, __float2half2_rn(0.f));
    return *reinterpret_cast<uint32_t*>(&x);
}

#define LDMX4(r0, r1, r2, r3, addr) \
    asm volatile("ldmatrix.sync.aligned.m8n8.x4.shared.b16 {%0,%1,%2,%3}, [%4];" \
        : "=r"(r0), "=r"(r1), "=r"(r2), "=r"(r3) : "r"(addr))

#define MMA_F16(c, A, b0, b1) \
    asm volatile("mma.sync.aligned.m16n8k16.row.col.f32.f16.f16.f32 " \
        "{%0,%1,%2,%3},{%4,%5,%6,%7},{%8,%9},{%0,%1,%2,%3};" \
        : "+f"((c)[0]), "+f"((c)[1]), "+f"((c)[2]), "+f"((c)[3]) \
        : "r"((A)[0]), "r"((A)[1]), "r"((A)[2]), "r"((A)[3]), "r"(b0), "r"(b1))

#define CP_ASYNC16(dst, src) \
    asm volatile("cp.async.cg.shared.global [%0], [%1], 16;" :: "r"(dst), "l"(src) : "memory")
#define CP_COMMIT() asm volatile("cp.async.commit_group;" ::: "memory")
#define CP_WAIT1()  asm volatile("cp.async.wait_group 1;" ::: "memory")

// ---------------- merged prep kernel ----------------------------------------
// grid = 1024 (uv) + 8 (qc) + 64 (W-transpose tiles), 512 threads.
__global__ void prep_all_kernel(const float* __restrict__ x,
                                const float* __restrict__ g0w,
                                const float* __restrict__ g0b,
                                const float* __restrict__ g1w,
                                const float* __restrict__ qst,
                                const float* __restrict__ g1b) {
    const int bid = blockIdx.x;
    const int t = threadIdx.x;
    __shared__ float xs[KK];
    __shared__ float qs[QQ];
    __shared__ __half tile[64 * 72];

    if (bid < BB * DD) {
        // ---- u / v
        if (t < KK) xs[t] = x[bid * KK + t];
        __syncthreads();
        float u = 0.f, v = 0.f;
        if (t < G0V) {
            u = g0b[t];
#pragma unroll
            for (int k = 0; k < KK; ++k) {
                u += xs[k] * g0w[k * G0V + t];
                v += xs[k] * g0w[(k + KK) * G0V + t];
            }
        }
        g_u_h[bid * KP + t] = __float2half(u);
        g_v_h[bid * KP + t] = __float2half(v);
    } else if (bid < BB * DD + BB) {
        // ---- qc
        const int b = bid - BB * DD;
        if (t < QQ) qs[t] = qst[b * QQ + t];
        __syncthreads();
        float s = g1b[t];
#pragma unroll 4
        for (int q = 0; q < QQ; ++q)
            s += qs[q] * g1w[(G0V + q) * G1V + t];
        g_qc[b * G1V + t] = s;
    } else {
        // ---- W transpose: 64x64 tile, coalesced read + coalesced write
        const int wb = bid - (BB * DD + BB);        // 0..63
        const int kt = (wb >> 3) * 64, nt = (wb & 7) * 64;
        const int w = t >> 5, lane = t & 31;        // 16 warps
#pragma unroll
        for (int i = 0; i < 4; ++i) {
            const int r = w * 4 + i;
            const int k = kt + r;
            float2 v = make_float2(0.f, 0.f);
            if (k < G0V) v = *(const float2*)(g1w + (size_t)k * G1V + nt + lane * 2);
            tile[r * 72 + lane * 2]     = __float2half(v.x);
            tile[r * 72 + lane * 2 + 1] = __float2half(v.y);
        }
        __syncthreads();
#pragma unroll
        for (int i = 0; i < 4; ++i) {
            const int nl = w * 4 + i;
            __half2 h = __halves2half2(tile[(lane * 2) * 72 + nl],
                                       tile[(lane * 2 + 1) * 72 + nl]);
            *(__half2*)(g_wt + (size_t)(nt + nl) * KP + kt + lane * 2) = h;
        }
    }
}

// ---------------- dominant kernel: 3-stage pipelined HMMA GEMM (fp16) -------
// (round-7 best configuration; epilogue pre-reduces the a-pair)
#define OFF_V      0
#define OFF_QC     2048
#define OFF_RED    2560
#define OFF_STAGE  6784
#define T_PITCH    80
#define TILE_SZ    (128 * T_PITCH)      // 10240
#define STAGE_SZ   (3 * TILE_SZ)        // A0 A1 W = 30720
#define NSTAGE     3
#define SMEM_MMA_TOTAL (OFF_STAGE + NSTAGE * STAGE_SZ)   // 98944

__global__ __launch_bounds__(512, 1) void rn_mma_kernel() {
    extern __shared__ char smem[];
    const uint32_t sbase = smem_u32(smem);
    const int t = threadIdx.x;
    const int lane = t & 31, warp = t >> 5;
    const int wc = warp >> 2, wn = warp & 3;
    const int nq = blockIdx.x, ap = blockIdx.y, b = blockIdx.z;

    if (t < 128) {
        ((uint4*)smem)[t] =
            ((const uint4*)(g_v_h + (size_t)(b * DD + ap * 2) * KP))[t];
    } else if (t < 256) {
        ((float*)(smem + OFF_QC))[t - 128] = g_qc[b * G1V + nq * 128 + (t - 128)];
    }

    const int row = t >> 2, seg = t & 3;
    const __half* uptr = g_u_h + (size_t)(b * DD + row) * KP + seg * 8;
    const __half* wptr = g_wt  + (size_t)(nq * 128 + row) * KP + seg * 8;
    const uint32_t arow = (uint32_t)row * T_PITCH + seg * 16;

    auto stAddr = [&](int s) { return sbase + OFF_STAGE + s * STAGE_SZ; };

    auto buildA = [&](int kb, int s, const uint4& uu) {
        char* sb = smem + OFF_STAGE + s * STAGE_SZ;
        uint4 v0 = *(const uint4*)(smem + kb * 64 + seg * 16);
        uint4 v1 = *(const uint4*)(smem + 1024 + kb * 64 + seg * 16);
        uint4 a0, a1;
        a0.x = relu_add2h(uu.x, v0.x); a0.y = relu_add2h(uu.y, v0.y);
        a0.z = relu_add2h(uu.z, v0.z); a0.w = relu_add2h(uu.w, v0.w);
        a1.x = relu_add2h(uu.x, v1.x); a1.y = relu_add2h(uu.y, v1.y);
        a1.z = relu_add2h(uu.z, v1.z); a1.w = relu_add2h(uu.w, v1.w);
        *(uint4*)(sb + arow)           = a0;
        *(uint4*)(sb + TILE_SZ + arow) = a1;
    };

    const int grp = lane >> 3, rin = lane & 7;
    const uint32_t aOff = (uint32_t)(wc * 32 + rin + (grp & 1) * 8) * T_PITCH + (grp >> 1) * 16;
    const uint32_t bOff = (uint32_t)(wn * 32 + rin + (grp >> 1) * 8) * T_PITCH + (grp & 1) * 16;

    float acc[2][2][4][4];
#pragma unroll
    for (int a = 0; a < 2; ++a)
#pragma unroll
        for (int mi = 0; mi < 2; ++mi)
#pragma unroll
            for (int ni = 0; ni < 4; ++ni)
#pragma unroll
                for (int j = 0; j < 4; ++j) acc[a][mi][ni][j] = 0.f;

    CP_ASYNC16(stAddr(0) + 2 * TILE_SZ + arow, wptr);
    CP_COMMIT();
    CP_ASYNC16(stAddr(1) + 2 * TILE_SZ + arow, wptr + 32);
    CP_COMMIT();
    __syncthreads();
    {
        uint4 uu = *(const uint4*)(uptr);
        buildA(0, 0, uu);
    }
    CP_WAIT1();
    __syncthreads();

    uint4 pu;
    for (int it = 0; it < 16; ++it) {
        const uint32_t sb = stAddr(it % NSTAGE);
        if (it + 2 < 16) {
            const uint32_t nst = stAddr((it + 2) % NSTAGE);
            CP_ASYNC16(nst + 2 * TILE_SZ + arow, wptr + (it + 2) * 32);
        }
        CP_COMMIT();
        if (it + 1 < 16) pu = *(const uint4*)(uptr + (it + 1) * 32);

#pragma unroll
        for (int kk = 0; kk < 2; ++kk) {
            uint32_t BW[4][2];
            const uint32_t bwA = sb + 2 * TILE_SZ + bOff + kk * 32;
            LDMX4(BW[0][0], BW[0][1], BW[1][0], BW[1][1], bwA);
            LDMX4(BW[2][0], BW[2][1], BW[3][0], BW[3][1], bwA + 16 * T_PITCH);
#pragma unroll
            for (int a = 0; a < 2; ++a) {
                uint32_t AF[2][4];
                const uint32_t aa = sb + a * TILE_SZ + aOff + kk * 32;
                LDMX4(AF[0][0], AF[0][1], AF[0][2], AF[0][3], aa);
                LDMX4(AF[1][0], AF[1][1], AF[1][2], AF[1][3], aa + 16 * T_PITCH);
#pragma unroll
                for (int mi = 0; mi < 2; ++mi)
#pragma unroll
                    for (int ni = 0; ni < 4; ++ni)
                        MMA_F16(acc[a][mi][ni], AF[mi], BW[ni][0], BW[ni][1]);
            }
        }
        if (it + 1 < 16) buildA(it + 1, (it + 1) % NSTAGE, pu);
        CP_WAIT1();
        __syncthreads();
    }

    // ---- epilogue: relu(D + qc), sum over c AND the a-pair (deterministic) --
    const float* qcs = (const float*)(smem + OFF_QC);
    float* red = (float*)(smem + OFF_RED);
    float qn0[4], qn1[4];
    const int nc0 = wn * 32 + (lane & 3) * 2;
#pragma unroll
    for (int ni = 0; ni < 4; ++ni) {
        qn0[ni] = qcs[nc0 + ni * 8];
        qn1[ni] = qcs[nc0 + ni * 8 + 1];
    }
#pragma unroll
    for (int a = 0; a < 2; ++a) {
        float s0[4], s1[4];
#pragma unroll
        for (int ni = 0; ni < 4; ++ni) {
            s0[ni] = 0.f; s1[ni] = 0.f;
#pragma unroll
            for (int mi = 0; mi < 2; ++mi) {
                s0[ni] += fmaxf(acc[a][mi][ni][0] + qn0[ni], 0.f)
                        + fmaxf(acc[a][mi][ni][2] + qn0[ni], 0.f);
                s1[ni] += fmaxf(acc[a][mi][ni][1] + qn1[ni], 0.f)
                        + fmaxf(acc[a][mi][ni][3] + qn1[ni], 0.f);
            }
        }
#pragma unroll
        for (int off = 4; off < 32; off <<= 1)
#pragma unroll
            for (int ni = 0; ni < 4; ++ni) {
                s0[ni] += __shfl_xor_sync(0xffffffffu, s0[ni], off);
                s1[ni] += __shfl_xor_sync(0xffffffffu, s1[ni], off);
            }
        if (lane < 4) {
#pragma unroll
            for (int ni = 0; ni < 4; ++ni) {
                red[(wc * 2 + a) * 128 + wn * 32 + ni * 8 + lane * 2]     = s0[ni];
                red[(wc * 2 + a) * 128 + wn * 32 + ni * 8 + lane * 2 + 1] = s1[ni];
            }
        }
    }
    __syncthreads();
    if (t < 128) {
        float s = 0.f;
#pragma unroll
        for (int r = 0; r < 8; ++r) s += red[r * 128 + t];
        g_part[((size_t)(b * 64) + ap) * G1V + nq * 128 + t] = s;
    }
}

// ---------------- tail kernels -----------------------------------------------
// k_f1 (fused xg): grid (4 nq, 8 b), 1024 thr.
// Phase 1: xg[i] = sum_ap part[b,ap,i] (2 thr/entry, 32 ap each, fixed order).
// Phase 2: f1 outputs nq*128..+127 with 8-way split-K over smem xg.
__global__ __launch_bounds__(1024) void k_f1(const float* __restrict__ f1w,
                                             const float* __restrict__ f1b) {
    const int nq = blockIdx.x, b = blockIdx.y;
    const int t = threadIdx.x;   // 1024
    __shared__ float xs[G1V];
    __shared__ float red[1024];

    // ---- phase 1: xg over 64 pre-reduced ap rows
    {
        const int i = t & 511, half = t >> 9;     // 2 threads per entry
        const float* p = g_part + ((size_t)(b * 64) + half * 32) * G1V + i;
        float s = 0.f;
#pragma unroll 16
        for (int a = 0; a < 32; ++a) s += p[(size_t)a * G1V];
        red[t] = s;
    }
    __syncthreads();
    if (t < G1V) xs[t] = red[t] + red[t + 512];
    __syncthreads();

    // ---- phase 2: f1, 8 threads/output, K split 8x64
    const int j = nq * 128 + (t & 127);
    const int q = t >> 7, base = q * 64;   // q 0..7
    float s = 0.f;
#pragma unroll 16
    for (int i = 0; i < 64; ++i)
        s += xs[base + i] * f1w[(size_t)(base + i) * F1V + j];
    red[t] = s;
    __syncthreads();
    if (t < 128) {
        float r = f1b[nq * 128 + t];
#pragma unroll
        for (int q2 = 0; q2 < 8; ++q2) r += red[q2 * 128 + t];
        g_h1[b * F1V + nq * 128 + t] = fmaxf(r, 0.f);
    }
}

// k_f2: grid (8 jb, 8 b), 1024 thr; 8 threads/output, K split 8x64.
__global__ __launch_bounds__(1024) void k_f2(const float* __restrict__ f2w,
                                             const float* __restrict__ f2b) {
    const int jb = blockIdx.x, b = blockIdx.y;
    const int t = threadIdx.x;   // 1024
    __shared__ float hs[F1V];
    __shared__ float red[1024];
    if (t < F1V) hs[t] = g_h1[b * F1V + t];
    __syncthreads();
    const int j = jb * 128 + (t & 127);
    const int q = t >> 7, base = q * 64;
    float s = 0.f;
#pragma unroll 16
    for (int i = 0; i < 64; ++i)
        s += hs[base + i] * f2w[(size_t)(base + i) * F2V + j];
    red[t] = s;
    __syncthreads();
    if (t < 128) {
        float r = f2b[jb * 128 + t];
#pragma unroll
        for (int q2 = 0; q2 < 8; ++q2) r += red[q2 * 128 + t];
        g_h2[b * F2V + jb * 128 + t] = fmaxf(r, 0.f);
    }
}

// k_f3: grid 8, 512 thr; 32 chunks of 32 per output column (fixed order).
__global__ __launch_bounds__(512) void k_f3(const float* __restrict__ f3w,
                                            const float* __restrict__ f3b,
                                            float* __restrict__ out) {
    const int b = blockIdx.x;
    const int t = threadIdx.x;   // 512
    __shared__ float h2s[F2V];
    __shared__ float lp[32 * OUTC];
    __shared__ float lg[OUTC];
    for (int i = t; i < F2V; i += 512) h2s[i] = g_h2[b * F2V + i];
    __syncthreads();
    {
        const int o  = t & 15;
        const int ch = t >> 4;   // 0..31
        float acc = (ch == 0) ? f3b[o] : 0.f;
#pragma unroll 16
        for (int i = ch * 32; i < ch * 32 + 32; ++i)
            acc += h2s[i] * f3w[i * OUTC + o];
        lp[ch * OUTC + o] = acc;
    }
    __syncthreads();
    if (t < OUTC) {
        float s = 0.f;
#pragma unroll
        for (int ch = 0; ch < 32; ++ch) s += lp[ch * OUTC + t];
        lg[t] = s;
    }
    __syncthreads();
    if (t < OUTC) {
        float m = lg[0];
#pragma unroll
        for (int i = 1; i < OUTC; ++i) m = fmaxf(m, lg[i]);
        float se = 0.f;
#pragma unroll
        for (int i = 0; i < OUTC; ++i) se += expf(lg[i] - m);
        out[b * OUTC + t] = lg[t] - m - logf(se);
    }
}

// ---------------- launch -----------------------------------------------------
extern "C" void kernel_launch(void* const* d_in, const int* in_sizes, int n_in,
                              void* d_out, int out_size) {
    const float* x   = (const float*)d_in[0];
    const float* qst = (const float*)d_in[1];
    const float* g0w = (const float*)d_in[2];
    const float* g0b = (const float*)d_in[3];
    const float* g1w = (const float*)d_in[4];
    const float* g1b = (const float*)d_in[5];
    const float* f1w = (const float*)d_in[6];
    const float* f1b = (const float*)d_in[7];
    const float* f2w = (const float*)d_in[8];
    const float* f2b = (const float*)d_in[9];
    const float* f3w = (const float*)d_in[10];
    const float* f3b = (const float*)d_in[11];
    float* out = (float*)d_out;

    static bool attr_set = false;
    if (!attr_set) {
        cudaFuncSetAttribute(rn_mma_kernel,
                             cudaFuncAttributeMaxDynamicSharedMemorySize, SMEM_MMA_TOTAL);
        attr_set = true;
    }

    prep_all_kernel<<<BB * DD + BB + 64, 512>>>(x, g0w, g0b, g1w, qst, g1b);
    rn_mma_kernel<<<dim3(4, 64, BB), 512, SMEM_MMA_TOTAL>>>();
    k_f1<<<dim3(4, BB), 1024>>>(f1w, f1b);
    k_f2<<<dim3(8, BB), 1024>>>(f2w, f2b);
    k_f3<<<BB, 512>>>(f3w, f3b, out);
}